// round 1
// baseline (speedup 1.0000x reference)
#include <cuda_runtime.h>

#define NN 100000
#define NE 3200000
#define FIN 512
#define HID 16
#define NC 64

// ---------------- scratch (static device globals; no allocation) ----------------
__device__ __align__(16) float g_bufA[NN * HID];
__device__ __align__(16) float g_bufB[NN * HID];
__device__ __align__(16) float g_hn[NN * HID];
__device__ float g_norm[NN];
__device__ int g_counts[NN + 1];
__device__ int g_rowptr[NN + 1];
__device__ int g_cursor[NN];
__device__ int g_colsrc[NE];

__constant__ __align__(16) float cW1[FIN * HID];
__constant__ __align__(16) float cB1[HID];
__constant__ __align__(16) float cW2[HID * NC];
__constant__ __align__(16) float cB2[NC];

// ---------------- small helpers ----------------
__device__ __forceinline__ float d4(float4 a, float4 b) {
    return a.x * b.x + a.y * b.y + a.z * b.z + a.w * b.w;
}
__device__ __forceinline__ void fma4(float4& a, float c, float4 b) {
    a.x += c * b.x; a.y += c * b.y; a.z += c * b.z; a.w += c * b.w;
}
__device__ __forceinline__ float4 scl4(float4 a, float c) {
    return make_float4(a.x * c, a.y * c, a.z * c, a.w * c);
}
__device__ __forceinline__ void comb4(float4& a, float pa, float4 b, float pb) {
    a.x = a.x * pa + b.x * pb; a.y = a.y * pa + b.y * pb;
    a.z = a.z * pa + b.z * pb; a.w = a.w * pa + b.w * pb;
}
__device__ __forceinline__ float4 shx4(float4 v, int off) {
    float4 r;
    r.x = __shfl_xor_sync(0xffffffffu, v.x, off, 8);
    r.y = __shfl_xor_sync(0xffffffffu, v.y, off, 8);
    r.z = __shfl_xor_sync(0xffffffffu, v.z, off, 8);
    r.w = __shfl_xor_sync(0xffffffffu, v.w, off, 8);
    return r;
}

// ---------------- CSR build ----------------
__global__ void k_zero(int n) {
    int i = blockIdx.x * blockDim.x + threadIdx.x;
    if (i < n) g_counts[i] = 0;
}

__global__ void k_hist(const int* __restrict__ ei, int E) {
    int e = blockIdx.x * blockDim.x + threadIdx.x;
    if (e < E) {
        int dst = ei[E + e];
        atomicAdd(&g_counts[dst], 1);
    }
}

// single-block exclusive scan over g_counts[0..NN) -> g_rowptr, g_cursor
__global__ void k_scan(int n) {
    __shared__ int ssum[1024];
    const int CH = 128;  // 1024*128 = 131072 >= NN
    int t = threadIdx.x;
    int base = t * CH;
    int s = 0;
    for (int i = 0; i < CH; i++) {
        int idx = base + i;
        if (idx < n) s += g_counts[idx];
    }
    ssum[t] = s;
    __syncthreads();
    // Hillis-Steele inclusive scan
    for (int off = 1; off < 1024; off <<= 1) {
        int v = (t >= off) ? ssum[t - off] : 0;
        __syncthreads();
        ssum[t] += v;
        __syncthreads();
    }
    int excl = (t == 0) ? 0 : ssum[t - 1];
    for (int i = 0; i < CH; i++) {
        int idx = base + i;
        if (idx < n) {
            g_rowptr[idx] = excl;
            g_cursor[idx] = excl;
            excl += g_counts[idx];
        }
    }
    if (t == 1023) g_rowptr[n] = ssum[1023];
}

__global__ void k_scatter(const int* __restrict__ ei, int E) {
    int e = blockIdx.x * blockDim.x + threadIdx.x;
    if (e < E) {
        int dst = ei[E + e];
        int src = ei[e];
        int pos = atomicAdd(&g_cursor[dst], 1);
        g_colsrc[pos] = src;
    }
}

// ---------------- h = relu(x @ W1 + b1), thread-per-row ----------------
__global__ void k_gemm1(const float4* __restrict__ x4, int n) {
    int row = blockIdx.x * blockDim.x + threadIdx.x;
    if (row >= n) return;
    const float4* w4 = (const float4*)cW1;  // [FIN][HID] -> 4 float4 per k
    float4 a0 = *(const float4*)&cB1[0];
    float4 a1 = *(const float4*)&cB1[4];
    float4 a2 = *(const float4*)&cB1[8];
    float4 a3 = *(const float4*)&cB1[12];
    const float4* xr = x4 + (long)row * (FIN / 4);
#pragma unroll 4
    for (int q = 0; q < FIN / 4; q++) {
        float4 xv = __ldg(xr + q);
        int kb = q * 4;  // scalar k base
#pragma unroll
        for (int c = 0; c < 4; c++) {
            float xs = (c == 0) ? xv.x : (c == 1) ? xv.y : (c == 2) ? xv.z : xv.w;
            const float4* w = w4 + (kb + c) * 4;
            fma4(a0, xs, w[0]);
            fma4(a1, xs, w[1]);
            fma4(a2, xs, w[2]);
            fma4(a3, xs, w[3]);
        }
    }
    float4* o4 = (float4*)&g_bufA[(long)row * HID];
    a0.x = fmaxf(a0.x, 0.f); a0.y = fmaxf(a0.y, 0.f); a0.z = fmaxf(a0.z, 0.f); a0.w = fmaxf(a0.w, 0.f);
    a1.x = fmaxf(a1.x, 0.f); a1.y = fmaxf(a1.y, 0.f); a1.z = fmaxf(a1.z, 0.f); a1.w = fmaxf(a1.w, 0.f);
    a2.x = fmaxf(a2.x, 0.f); a2.y = fmaxf(a2.y, 0.f); a2.z = fmaxf(a2.z, 0.f); a2.w = fmaxf(a2.w, 0.f);
    a3.x = fmaxf(a3.x, 0.f); a3.y = fmaxf(a3.y, 0.f); a3.z = fmaxf(a3.z, 0.f); a3.w = fmaxf(a3.w, 0.f);
    o4[0] = a0; o4[1] = a1; o4[2] = a2; o4[3] = a3;
}

// ---------------- L2 normalize: hn = h / max(||h||, eps), g_norm = max(||h||,eps) ----------------
__global__ void k_norm(int srcSel, int n) {
    int i = blockIdx.x * blockDim.x + threadIdx.x;
    if (i >= n) return;
    const float4* h4 = (const float4*)(srcSel ? g_bufB : g_bufA);
    float4 v0 = h4[i * 4 + 0], v1 = h4[i * 4 + 1], v2 = h4[i * 4 + 2], v3 = h4[i * 4 + 3];
    float ss = d4(v0, v0) + d4(v1, v1) + d4(v2, v2) + d4(v3, v3);
    float M = fmaxf(sqrtf(ss), 1e-12f);
    float inv = 1.0f / M;
    float4* hn4 = (float4*)g_hn;
    hn4[i * 4 + 0] = scl4(v0, inv);
    hn4[i * 4 + 1] = scl4(v1, inv);
    hn4[i * 4 + 2] = scl4(v2, inv);
    hn4[i * 4 + 3] = scl4(v3, inv);
    g_norm[i] = M;
}

// ---------------- AGNN layer: online segment-softmax + aggregate, 8 lanes/node ----------------
__global__ void k_agnn(const float* __restrict__ beta_p, int outSel, int n) {
    int g = threadIdx.x & 7;
    int node = (blockIdx.x * blockDim.x + threadIdx.x) >> 3;
    bool valid = node < n;
    int nd = valid ? node : 0;
    float beta = __ldg(beta_p);
    const float4* hn4 = (const float4*)g_hn;

    float4 d0 = hn4[nd * 4 + 0], d1 = hn4[nd * 4 + 1], d2 = hn4[nd * 4 + 2], d3 = hn4[nd * 4 + 3];

    float m = -1e30f, s = 0.f;
    float4 a0 = make_float4(0, 0, 0, 0), a1 = a0, a2 = a0, a3 = a0;

    if (g == 0 && valid) {
        // implicit self-loop: logit = beta * (hn . hn); x_self = hn * norm
        float sd = d4(d0, d0) + d4(d1, d1) + d4(d2, d2) + d4(d3, d3);
        m = beta * sd;
        s = 1.f;
        float nr = g_norm[nd];
        a0 = scl4(d0, nr); a1 = scl4(d1, nr); a2 = scl4(d2, nr); a3 = scl4(d3, nr);
    }

    int e0 = valid ? g_rowptr[nd] : 0;
    int e1 = valid ? g_rowptr[nd + 1] : 0;
    for (int e = e0 + g; e < e1; e += 8) {
        int sn = g_colsrc[e];
        float4 s0 = __ldg(&hn4[sn * 4 + 0]);
        float4 s1 = __ldg(&hn4[sn * 4 + 1]);
        float4 s2 = __ldg(&hn4[sn * 4 + 2]);
        float4 s3 = __ldg(&hn4[sn * 4 + 3]);
        float ns = __ldg(&g_norm[sn]);
        float cs = d4(d0, s0) + d4(d1, s1) + d4(d2, s2) + d4(d3, s3);
        float lg = beta * cs;
        if (lg <= m) {
            float p = __expf(lg - m);
            s += p;
            float w = p * ns;
            fma4(a0, w, s0); fma4(a1, w, s1); fma4(a2, w, s2); fma4(a3, w, s3);
        } else {
            float r = __expf(m - lg);  // exp(-1e30 - lg) -> 0 on first edge
            s = s * r + 1.f;
            comb4(a0, r, s0, ns); comb4(a1, r, s1, ns);
            comb4(a2, r, s2, ns); comb4(a3, r, s3, ns);
            m = lg;
        }
    }

    // combine 8-lane online-softmax states (xor butterfly, width 8)
#pragma unroll
    for (int off = 1; off < 8; off <<= 1) {
        float m2 = __shfl_xor_sync(0xffffffffu, m, off, 8);
        float s2 = __shfl_xor_sync(0xffffffffu, s, off, 8);
        float4 b0 = shx4(a0, off), b1 = shx4(a1, off), b2 = shx4(a2, off), b3 = shx4(a3, off);
        float M = fmaxf(m, m2);
        float pa = (m >= M) ? 1.f : __expf(m - M);
        float pb = (m2 >= M) ? 1.f : __expf(m2 - M);
        s = s * pa + s2 * pb;
        comb4(a0, pa, b0, pb); comb4(a1, pa, b1, pb);
        comb4(a2, pa, b2, pb); comb4(a3, pa, b3, pb);
        m = M;
    }

    if (valid && g < 4) {
        float inv = 1.0f / s;
        float4 av = (g == 0) ? a0 : (g == 1) ? a1 : (g == 2) ? a2 : a3;
        float4* out4 = (float4*)(outSel ? g_bufB : g_bufA);
        out4[node * 4 + g] = scl4(av, inv);
    }
}

// ---------------- out = log_softmax(h @ W2 + b2), warp-per-row ----------------
__global__ void k_gemm2(int srcSel, float* __restrict__ out, int n) {
    __shared__ float sW[HID * NC];
    __shared__ float sB[NC];
    for (int i = threadIdx.x; i < HID * NC; i += blockDim.x) sW[i] = cW2[i];
    if (threadIdx.x < NC) sB[threadIdx.x] = cB2[threadIdx.x];
    __syncthreads();

    int warp = threadIdx.x >> 5, lane = threadIdx.x & 31;
    int row = blockIdx.x * (blockDim.x >> 5) + warp;
    if (row >= n) return;

    const float* h = srcSel ? g_bufB : g_bufA;
    float hv = (lane < HID) ? h[(long)row * HID + lane] : 0.f;
    float z0 = sB[lane], z1 = sB[lane + 32];
#pragma unroll
    for (int k = 0; k < HID; k++) {
        float hk = __shfl_sync(0xffffffffu, hv, k);
        z0 += hk * sW[k * NC + lane];
        z1 += hk * sW[k * NC + 32 + lane];
    }
    float mx = fmaxf(z0, z1);
#pragma unroll
    for (int off = 16; off > 0; off >>= 1) mx = fmaxf(mx, __shfl_xor_sync(0xffffffffu, mx, off));
    float p = __expf(z0 - mx) + __expf(z1 - mx);
#pragma unroll
    for (int off = 16; off > 0; off >>= 1) p += __shfl_xor_sync(0xffffffffu, p, off);
    float lse = mx + __logf(p);
    out[(long)row * NC + lane] = z0 - lse;
    out[(long)row * NC + 32 + lane] = z1 - lse;
}

// ---------------- launch ----------------
extern "C" void kernel_launch(void* const* d_in, const int* in_sizes, int n_in,
                              void* d_out, int out_size) {
    const float* x = (const float*)d_in[0];
    const int* ei = (const int*)d_in[1];   // [2, E] int32 (JAX default non-x64)
    const float* W1 = (const float*)d_in[2];
    const float* b1 = (const float*)d_in[3];
    const float* W2 = (const float*)d_in[4];
    const float* b2 = (const float*)d_in[5];
    const float* beta1 = (const float*)d_in[6];
    const float* beta2 = (const float*)d_in[7];
    float* out = (float*)d_out;

    int N = in_sizes[0] / FIN;
    int E = in_sizes[1] / 2;

    cudaMemcpyToSymbolAsync(cW1, W1, FIN * HID * sizeof(float), 0, cudaMemcpyDeviceToDevice, 0);
    cudaMemcpyToSymbolAsync(cB1, b1, HID * sizeof(float), 0, cudaMemcpyDeviceToDevice, 0);
    cudaMemcpyToSymbolAsync(cW2, W2, HID * NC * sizeof(float), 0, cudaMemcpyDeviceToDevice, 0);
    cudaMemcpyToSymbolAsync(cB2, b2, NC * sizeof(float), 0, cudaMemcpyDeviceToDevice, 0);

    // CSR build (by dst)
    k_zero<<<(N + 255) / 256, 256>>>(N);
    k_hist<<<(E + 255) / 256, 256>>>(ei, E);
    k_scan<<<1, 1024>>>(N);
    k_scatter<<<(E + 255) / 256, 256>>>(ei, E);

    // MLP in
    k_gemm1<<<(N + 255) / 256, 256>>>((const float4*)x, N);

    // layer 1: bufA -> bufB
    k_norm<<<(N + 255) / 256, 256>>>(0, N);
    k_agnn<<<(N * 8 + 255) / 256, 256>>>(beta1, 1, N);

    // layer 2: bufB -> bufA
    k_norm<<<(N + 255) / 256, 256>>>(1, N);
    k_agnn<<<(N * 8 + 255) / 256, 256>>>(beta2, 0, N);

    // MLP out + log_softmax
    k_gemm2<<<(N + 7) / 8, 256>>>(0, out, N);
}